// round 7
// baseline (speedup 1.0000x reference)
#include <cuda_runtime.h>
#include <math.h>

#define NB   8
#define ND   768
#define NCH  3
#define NMIX 5
#define NS   10
#define NH   10

#define NT      24            // 32-wide tiles per ND
#define NPAIRS  300           // NT*(NT+1)/2 upper-triangular tile pairs

#define PI2f    6.283185307179586f
#define SQRT_L  1.2011224087864498f   // sqrt(log2(e))
#define ZITTERf 1e-4f

// Scratch (static device allocations are allowed; no cudaMalloc anywhere)
__device__ float4 g_pre[NB * NCH * NMIX * ND];        // {v, q, cos, sin} per (b,c,m,i)
__device__ float  g_hpart[NB * NCH * 6 * NH];         // per-(bc, i-tile) partial sums of relu(W1·tif)
__device__ float  g_wgt[NB * NCH * NMIX];             // gumbel-softmax mixture weights

// Triangular pair decode via constant LUT (branchless)
__constant__ unsigned char c_pair_it[NPAIRS] = {
    0,0,0,0,0,0,0,0,0,0,0,0,0,0,0,0,0,0,0,0,0,0,0,0,
    1,1,1,1,1,1,1,1,1,1,1,1,1,1,1,1,1,1,1,1,1,1,1,
    2,2,2,2,2,2,2,2,2,2,2,2,2,2,2,2,2,2,2,2,2,2,
    3,3,3,3,3,3,3,3,3,3,3,3,3,3,3,3,3,3,3,3,3,
    4,4,4,4,4,4,4,4,4,4,4,4,4,4,4,4,4,4,4,4,
    5,5,5,5,5,5,5,5,5,5,5,5,5,5,5,5,5,5,5,
    6,6,6,6,6,6,6,6,6,6,6,6,6,6,6,6,6,6,
    7,7,7,7,7,7,7,7,7,7,7,7,7,7,7,7,7,
    8,8,8,8,8,8,8,8,8,8,8,8,8,8,8,8,
    9,9,9,9,9,9,9,9,9,9,9,9,9,9,9,
    10,10,10,10,10,10,10,10,10,10,10,10,10,10,
    11,11,11,11,11,11,11,11,11,11,11,11,11,
    12,12,12,12,12,12,12,12,12,12,12,12,
    13,13,13,13,13,13,13,13,13,13,13,
    14,14,14,14,14,14,14,14,14,14,
    15,15,15,15,15,15,15,15,15,
    16,16,16,16,16,16,16,16,
    17,17,17,17,17,17,17,
    18,18,18,18,18,18,
    19,19,19,19,19,
    20,20,20,20,
    21,21,21,
    22,22,
    23
};
__constant__ unsigned char c_pair_jt[NPAIRS] = {
    0,1,2,3,4,5,6,7,8,9,10,11,12,13,14,15,16,17,18,19,20,21,22,23,
    1,2,3,4,5,6,7,8,9,10,11,12,13,14,15,16,17,18,19,20,21,22,23,
    2,3,4,5,6,7,8,9,10,11,12,13,14,15,16,17,18,19,20,21,22,23,
    3,4,5,6,7,8,9,10,11,12,13,14,15,16,17,18,19,20,21,22,23,
    4,5,6,7,8,9,10,11,12,13,14,15,16,17,18,19,20,21,22,23,
    5,6,7,8,9,10,11,12,13,14,15,16,17,18,19,20,21,22,23,
    6,7,8,9,10,11,12,13,14,15,16,17,18,19,20,21,22,23,
    7,8,9,10,11,12,13,14,15,16,17,18,19,20,21,22,23,
    8,9,10,11,12,13,14,15,16,17,18,19,20,21,22,23,
    9,10,11,12,13,14,15,16,17,18,19,20,21,22,23,
    10,11,12,13,14,15,16,17,18,19,20,21,22,23,
    11,12,13,14,15,16,17,18,19,20,21,22,23,
    12,13,14,15,16,17,18,19,20,21,22,23,
    13,14,15,16,17,18,19,20,21,22,23,
    14,15,16,17,18,19,20,21,22,23,
    15,16,17,18,19,20,21,22,23,
    16,17,18,19,20,21,22,23,
    17,18,19,20,21,22,23,
    18,19,20,21,22,23,
    19,20,21,22,23,
    20,21,22,23,
    21,22,23,
    22,23,
    23
};

// ---------------------------------------------------------------------------
// P: per-point precompute. v = 2*pi*inv_std[m]*x*sqrt(log2 e); q = -v*v/2;
//    (cos,sin) of 2*pi*mu[m]*x.  K(i,j) = exp2(v_i*v_j + q_i + q_j) * (c_i c_j + s_i s_j)
// ---------------------------------------------------------------------------
__global__ void k_pre(const float* __restrict__ xc,
                      const float* __restrict__ mu,
                      const float* __restrict__ inv_std) {
    int idx = blockIdx.x * blockDim.x + threadIdx.x;
    if (idx >= NB * NCH * NMIX * ND) return;
    int i = idx % ND;
    int m = (idx / ND) % NMIX;
    int c = (idx / (ND * NMIX)) % NCH;
    int b = idx / (ND * NMIX * NCH);
    float x = xc[(b * ND + i) * NCH + c];       // ndim==1 collapses
    float a = PI2f * inv_std[m];
    float v = a * x * SQRT_L;
    float q = -0.5f * v * v;
    float s, co;
    sincosf(PI2f * mu[m] * x, &s, &co);
    g_pre[idx] = make_float4(v, q, co, s);
}

// ---------------------------------------------------------------------------
// F: feature[b,i,c,m] = sum_j K_m(i,j) y_j + zitter*y_i, then h = relu(W1·[f,y]+b1),
//    deterministic per-tile partial sum of h (no atomics).
// grid = (6 i-tiles, 24 bc), 128 threads, one i per thread.
// y_j is pre-folded into the shared j-tile: sp = {v_j, q_j, c_j*y_j, s_j*y_j}.
// ---------------------------------------------------------------------------
__global__ void __launch_bounds__(128) k_feat(const float* __restrict__ yc,
                                              const float* __restrict__ W1,
                                              const float* __restrict__ b1) {
    int tile = blockIdx.x;
    int bc   = blockIdx.y;
    int tid  = threadIdx.x;
    int i    = tile * 128 + tid;
    int b    = bc / NCH, c = bc % NCH;

    __shared__ float4 sp[NMIX][256];

    float4 Pi[NMIX];
#pragma unroll
    for (int m = 0; m < NMIX; m++) Pi[m] = g_pre[(bc * NMIX + m) * ND + i];

    float f[NMIX] = {0.f, 0.f, 0.f, 0.f, 0.f};

    for (int ch = 0; ch < ND; ch += 256) {
        __syncthreads();
        for (int jj = tid; jj < 256; jj += 128) {
            int j = ch + jj;
            float yj = yc[(b * ND + j) * NCH + c];
#pragma unroll
            for (int m = 0; m < NMIX; m++) {
                float4 p = g_pre[(bc * NMIX + m) * ND + j];
                sp[m][jj] = make_float4(p.x, p.y, p.z * yj, p.w * yj);
            }
        }
        __syncthreads();
        for (int jj = 0; jj < 256; jj++) {
#pragma unroll
            for (int m = 0; m < NMIX; m++) {
                float4 Pj = sp[m][jj];
                float t   = fmaf(Pi[m].x, Pj.x, Pi[m].y + Pj.y);  // v_i v_j + q_i + q_j (<= ~0)
                float ccy = fmaf(Pi[m].w, Pj.w, Pi[m].z * Pj.z);  // (c_i c_j + s_i s_j) * y_j
                f[m] = fmaf(exp2f(t), ccy, f[m]);
            }
        }
    }

    float yi = yc[(b * ND + i) * NCH + c];
#pragma unroll
    for (int m = 0; m < NMIX; m++) f[m] = fmaf(ZITTERf, yi, f[m]);

    // h_k = relu(b1 + W1 · [f0..f4, y])
    float hk[NH];
#pragma unroll
    for (int k = 0; k < NH; k++) {
        float acc = b1[k];
#pragma unroll
        for (int m = 0; m < NMIX; m++) acc = fmaf(W1[k * 6 + m], f[m], acc);
        acc = fmaf(W1[k * 6 + 5], yi, acc);
        hk[k] = fmaxf(acc, 0.0f);
    }

    // deterministic block reduction of hk over the 128 i's of this tile
    __shared__ float red[4][NH];
    int lane = tid & 31, wid = tid >> 5;
#pragma unroll
    for (int k = 0; k < NH; k++) {
        float v = hk[k];
#pragma unroll
        for (int o = 16; o > 0; o >>= 1) v += __shfl_down_sync(0xffffffffu, v, o);
        if (lane == 0) red[wid][k] = v;
    }
    __syncthreads();
    if (tid < NH) {
        float s = red[0][tid] + red[1][tid] + red[2][tid] + red[3][tid];
        g_hpart[(bc * 6 + tile) * NH + tid] = s;
    }
}

// ---------------------------------------------------------------------------
// M: mean over nd, MLP tail (W2..W5), gumbel-softmax sampling -> weights.
// Single block of 256 threads. All work here is microscopic.
// ---------------------------------------------------------------------------
__global__ void __launch_bounds__(256) k_mlp(const float* __restrict__ unif,
                                             const float* __restrict__ W2, const float* __restrict__ b2,
                                             const float* __restrict__ W3, const float* __restrict__ b3,
                                             const float* __restrict__ W4, const float* __restrict__ b4,
                                             const float* __restrict__ W5, const float* __restrict__ b5) {
    int tid = threadIdx.x;
    __shared__ float sHm[NB * NCH][NH];
    if (tid < NB * NCH * NH) {
        int bc = tid / NH, k = tid % NH;
        float s = 0.f;
#pragma unroll
        for (int t = 0; t < 6; t++) s += g_hpart[(bc * 6 + t) * NH + k];
        sHm[bc][k] = s * (1.0f / ND);
    }
    __syncthreads();

    __shared__ float sLL[NB][NCH * NMIX];
    if (tid < NB) {
        int b = tid;
        float hm[NCH * NH];
#pragma unroll
        for (int c = 0; c < NCH; c++)
#pragma unroll
            for (int k = 0; k < NH; k++) hm[c * NH + k] = sHm[b * NCH + c][k];
        float h2[NH], h3[NH], h4[NH];
#pragma unroll
        for (int k = 0; k < NH; k++) {
            float a = b2[k];
            for (int j = 0; j < NCH * NH; j++) a = fmaf(W2[k * (NCH * NH) + j], hm[j], a);
            h2[k] = fmaxf(a, 0.f);
        }
#pragma unroll
        for (int k = 0; k < NH; k++) {
            float a = b3[k];
            for (int j = 0; j < NH; j++) a = fmaf(W3[k * NH + j], h2[j], a);
            h3[k] = fmaxf(a, 0.f);
        }
#pragma unroll
        for (int k = 0; k < NH; k++) {
            float a = b4[k];
            for (int j = 0; j < NH; j++) a = fmaf(W4[k * NH + j], h3[j], a);
            h4[k] = fmaxf(a, 0.f);
        }
#pragma unroll
        for (int o = 0; o < NCH * NMIX; o++) {
            float a = b5[o];
            for (int k = 0; k < NH; k++) a = fmaf(W5[o * NH + k], h4[k], a);
            sLL[b][o] = a;
        }
    }
    __syncthreads();

    if (tid < NB * NCH) {
        int b = tid / NCH, c = tid % NCH;
        float ws[NMIX] = {0.f, 0.f, 0.f, 0.f, 0.f};
        for (int s = 0; s < NS; s++) {
            float z[NMIX], mx = -1e30f;
#pragma unroll
            for (int m = 0; m < NMIX; m++) {
                float u = unif[((b * NS + s) * NCH + c) * NMIX + m];
                float g = -logf(-logf(u + 1e-20f));
                z[m] = (g + sLL[b][c * NMIX + m]) * 10.0f;   // / TEMP(0.1)
                mx = fmaxf(mx, z[m]);
            }
            float e[NMIX], sum = 0.f;
#pragma unroll
            for (int m = 0; m < NMIX; m++) { e[m] = expf(z[m] - mx); sum += e[m]; }
            float inv = 1.0f / sum;
#pragma unroll
            for (int m = 0; m < NMIX; m++) ws[m] = fmaf(e[m], inv, ws[m]);
        }
#pragma unroll
        for (int m = 0; m < NMIX; m++)
            g_wgt[tid * NMIX + m] = ws[m] * (1.0f / NS);
    }
}

// ---------------------------------------------------------------------------
// O: out[b,i,j,c] = sum_m w[b,c,m] K_m(i,j) + (zitter + clip(likerr_c)^2) * [i==j]
// SYMMETRY: out[b,i,j,c] == out[b,j,i,c]. Compute only upper-triangular 32x32
// tile pairs (it<=jt): grid = (300 pairs, NB). Mirror block written coalesced
// via a padded smem transpose (stride 99 floats -> conflict-free).
// Mixture weight w is pre-folded into the j-tile: sJ = {v, q, w*c, w*s},
// saving one FMUL per inner eval.
// ---------------------------------------------------------------------------
__global__ void __launch_bounds__(256) k_out(const float* __restrict__ likerr,
                                             float* __restrict__ out) {
    int tid = threadIdx.x;
    int b   = blockIdx.y;
    int it  = c_pair_it[blockIdx.x];
    int jt  = c_pair_jt[blockIdx.x];

    __shared__ float4 sI[15 * 33];
    __shared__ float4 sJ[15 * 33];
    __shared__ float  sT[32 * 99];   // transpose staging: [il][jl*3+c], pitch 99
    __shared__ float  sD[NCH];

    for (int idx = tid; idx < 15 * 32; idx += 256) {
        int p = idx >> 5, il = idx & 31;
        sI[p * 33 + il] = g_pre[(b * 15 + p) * ND + it * 32 + il];
        float4 pj = g_pre[(b * 15 + p) * ND + jt * 32 + il];
        float  w  = g_wgt[b * 15 + p];
        sJ[p * 33 + il] = make_float4(pj.x, pj.y, pj.z * w, pj.w * w);
    }
    if (tid < NCH) {
        float lk = fminf(fmaxf(likerr[tid], 0.1f), 1.0f);
        sD[tid] = ZITTERf + lk * lk;
    }
    __syncthreads();

    int tx = tid & 15, ty = tid >> 4;
    float acc[NCH][4];
#pragma unroll
    for (int c = 0; c < NCH; c++)
#pragma unroll
        for (int k = 0; k < 4; k++) acc[c][k] = 0.f;

#pragma unroll
    for (int c = 0; c < NCH; c++) {
#pragma unroll
        for (int m = 0; m < NMIX; m++) {
            int p = c * NMIX + m;
            float4 Pi0 = sI[p * 33 + ty];
            float4 Pi1 = sI[p * 33 + ty + 16];
            float4 Pj0 = sJ[p * 33 + tx];
            float4 Pj1 = sJ[p * 33 + tx + 16];
#define EVAL(PI, PJ, K)                                                     \
            {                                                               \
                float t  = fmaf((PI).x, (PJ).x, (PI).y + (PJ).y);           \
                float cw = fmaf((PI).w, (PJ).w, (PI).z * (PJ).z);           \
                acc[c][K] = fmaf(exp2f(t), cw, acc[c][K]);                  \
            }
            EVAL(Pi0, Pj0, 0)
            EVAL(Pi0, Pj1, 1)
            EVAL(Pi1, Pj0, 2)
            EVAL(Pi1, Pj1, 3)
#undef EVAL
        }
    }

    // direct block (rows it-tile, cols jt-tile), coalesced in tx
#pragma unroll
    for (int ii = 0; ii < 2; ii++) {
        int gi = it * 32 + ty + ii * 16;
#pragma unroll
        for (int jj = 0; jj < 2; jj++) {
            int gj = jt * 32 + tx + jj * 16;
            int base = ((b * ND + gi) * ND + gj) * NCH;
            bool diag = (gi == gj);
#pragma unroll
            for (int c = 0; c < NCH; c++) {
                float v = acc[c][ii * 2 + jj];
                if (diag) v += sD[c];
                out[base + c] = v;
            }
        }
    }

    if (it != jt) {
        // stage block[il][jl][c] into smem
#pragma unroll
        for (int ii = 0; ii < 2; ii++)
#pragma unroll
            for (int jj = 0; jj < 2; jj++)
#pragma unroll
                for (int c = 0; c < NCH; c++)
                    sT[(ty + ii * 16) * 99 + (tx + jj * 16) * 3 + c] = acc[c][ii * 2 + jj];
        __syncthreads();
        // mirror block (rows jt-tile, cols it-tile): M[r][s] = block[s][r]
#pragma unroll
        for (int ii = 0; ii < 2; ii++) {
            int gi = jt * 32 + ty + ii * 16;     // row in mirror block
#pragma unroll
            for (int jj = 0; jj < 2; jj++) {
                int gj = it * 32 + tx + jj * 16; // col in mirror block
                int base = ((b * ND + gi) * ND + gj) * NCH;
#pragma unroll
                for (int c = 0; c < NCH; c++)
                    out[base + c] = sT[(tx + jj * 16) * 99 + (ty + ii * 16) * 3 + c];
            }
        }
    }
}

// ---------------------------------------------------------------------------
extern "C" void kernel_launch(void* const* d_in, const int* in_sizes, int n_in,
                              void* d_out, int out_size) {
    const float* xc      = (const float*)d_in[0];
    const float* yc      = (const float*)d_in[1];
    const float* mu      = (const float*)d_in[2];
    const float* inv_std = (const float*)d_in[3];
    const float* likerr  = (const float*)d_in[4];
    const float* unif    = (const float*)d_in[5];
    const float* W1 = (const float*)d_in[6],  *b1 = (const float*)d_in[7];
    const float* W2 = (const float*)d_in[8],  *b2 = (const float*)d_in[9];
    const float* W3 = (const float*)d_in[10], *b3 = (const float*)d_in[11];
    const float* W4 = (const float*)d_in[12], *b4 = (const float*)d_in[13];
    const float* W5 = (const float*)d_in[14], *b5 = (const float*)d_in[15];
    float* out = (float*)d_out;

    int npre = NB * NCH * NMIX * ND;
    k_pre<<<(npre + 255) / 256, 256>>>(xc, mu, inv_std);
    k_feat<<<dim3(6, NB * NCH), 128>>>(yc, W1, b1);
    k_mlp<<<1, 256>>>(unif, W2, b2, W3, b3, W4, b4, W5, b5);
    k_out<<<dim3(NPAIRS, NB), 256>>>(likerr, out);
}

// round 9
// speedup vs baseline: 1.2288x; 1.2288x over previous
#include <cuda_runtime.h>
#include <math.h>

#define NB   8
#define ND   768
#define NCH  3
#define NMIX 5
#define NS   10
#define NH   10

#define NT      24            // 32-wide tiles per ND
#define NPAIRS  300           // NT*(NT+1)/2 upper-triangular tile pairs
#define NFT     24            // k_feat i-tiles (32 i's each)

#define PI2f    6.283185307179586f
#define SQRT_L  1.2011224087864498f   // sqrt(log2(e))
#define ZITTERf 1e-4f

__device__ float4 g_pre[NB * NCH * NMIX * ND];        // {v, q, cos, sin} per (b,c,m,i)
__device__ float  g_hpart[NB * NCH * NFT * NH];       // per-(bc, i-tile) partial sums of relu(W1·tif)
__device__ float  g_wgt[NB * NCH * NMIX];             // gumbel-softmax mixture weights

// Triangular pair decode via constant LUT (branchless)
__constant__ unsigned char c_pair_it[NPAIRS] = {
    0,0,0,0,0,0,0,0,0,0,0,0,0,0,0,0,0,0,0,0,0,0,0,0,
    1,1,1,1,1,1,1,1,1,1,1,1,1,1,1,1,1,1,1,1,1,1,1,
    2,2,2,2,2,2,2,2,2,2,2,2,2,2,2,2,2,2,2,2,2,2,
    3,3,3,3,3,3,3,3,3,3,3,3,3,3,3,3,3,3,3,3,3,
    4,4,4,4,4,4,4,4,4,4,4,4,4,4,4,4,4,4,4,4,
    5,5,5,5,5,5,5,5,5,5,5,5,5,5,5,5,5,5,5,
    6,6,6,6,6,6,6,6,6,6,6,6,6,6,6,6,6,6,
    7,7,7,7,7,7,7,7,7,7,7,7,7,7,7,7,7,
    8,8,8,8,8,8,8,8,8,8,8,8,8,8,8,8,
    9,9,9,9,9,9,9,9,9,9,9,9,9,9,9,
    10,10,10,10,10,10,10,10,10,10,10,10,10,10,
    11,11,11,11,11,11,11,11,11,11,11,11,11,
    12,12,12,12,12,12,12,12,12,12,12,12,
    13,13,13,13,13,13,13,13,13,13,13,
    14,14,14,14,14,14,14,14,14,14,
    15,15,15,15,15,15,15,15,15,
    16,16,16,16,16,16,16,16,
    17,17,17,17,17,17,17,
    18,18,18,18,18,18,
    19,19,19,19,19,
    20,20,20,20,
    21,21,21,
    22,22,
    23
};
__constant__ unsigned char c_pair_jt[NPAIRS] = {
    0,1,2,3,4,5,6,7,8,9,10,11,12,13,14,15,16,17,18,19,20,21,22,23,
    1,2,3,4,5,6,7,8,9,10,11,12,13,14,15,16,17,18,19,20,21,22,23,
    2,3,4,5,6,7,8,9,10,11,12,13,14,15,16,17,18,19,20,21,22,23,
    3,4,5,6,7,8,9,10,11,12,13,14,15,16,17,18,19,20,21,22,23,
    4,5,6,7,8,9,10,11,12,13,14,15,16,17,18,19,20,21,22,23,
    5,6,7,8,9,10,11,12,13,14,15,16,17,18,19,20,21,22,23,
    6,7,8,9,10,11,12,13,14,15,16,17,18,19,20,21,22,23,
    7,8,9,10,11,12,13,14,15,16,17,18,19,20,21,22,23,
    8,9,10,11,12,13,14,15,16,17,18,19,20,21,22,23,
    9,10,11,12,13,14,15,16,17,18,19,20,21,22,23,
    10,11,12,13,14,15,16,17,18,19,20,21,22,23,
    11,12,13,14,15,16,17,18,19,20,21,22,23,
    12,13,14,15,16,17,18,19,20,21,22,23,
    13,14,15,16,17,18,19,20,21,22,23,
    14,15,16,17,18,19,20,21,22,23,
    15,16,17,18,19,20,21,22,23,
    16,17,18,19,20,21,22,23,
    17,18,19,20,21,22,23,
    18,19,20,21,22,23,
    19,20,21,22,23,
    20,21,22,23,
    21,22,23,
    22,23,
    23
};

// ---------------------------------------------------------------------------
// P: per-point precompute.
// ---------------------------------------------------------------------------
__global__ void k_pre(const float* __restrict__ xc,
                      const float* __restrict__ mu,
                      const float* __restrict__ inv_std) {
    int idx = blockIdx.x * blockDim.x + threadIdx.x;
    if (idx >= NB * NCH * NMIX * ND) return;
    int i = idx % ND;
    int m = (idx / ND) % NMIX;
    int c = (idx / (ND * NMIX)) % NCH;
    int b = idx / (ND * NMIX * NCH);
    float x = xc[(b * ND + i) * NCH + c];
    float a = PI2f * inv_std[m];
    float v = a * x * SQRT_L;
    float q = -0.5f * v * v;
    float s, co;
    sincosf(PI2f * mu[m] * x, &s, &co);
    g_pre[idx] = make_float4(v, q, co, s);
}

// ---------------------------------------------------------------------------
// F: feature + W1/relu + per-tile partial mean.
// grid = (24 i-tiles of 32, 24 bc), 256 threads = 32 i's x 8 j-slices.
// Each slice accumulates f over its 96 j's; slices combined in FIXED order
// through padded smem (deterministic). Warp 0 finishes hk + reduction.
// ---------------------------------------------------------------------------
__global__ void __launch_bounds__(256) k_feat(const float* __restrict__ yc,
                                              const float* __restrict__ W1,
                                              const float* __restrict__ b1) {
    int tile  = blockIdx.x;          // 0..23
    int bc    = blockIdx.y;          // 0..23
    int tid   = threadIdx.x;
    int il    = tid & 31;            // i within tile
    int slice = tid >> 5;            // 0..7 j-slice
    int b = bc / NCH, c = bc % NCH;
    int i = tile * 32 + il;

    __shared__ float4 sp[NMIX][256];        // j-chunk: {v, q, c*y, s*y}
    __shared__ float  fpart[NMIX][8][33];   // slice partials, padded

    float4 Pi[NMIX];
#pragma unroll
    for (int m = 0; m < NMIX; m++) Pi[m] = g_pre[(bc * NMIX + m) * ND + i];

    float f[NMIX] = {0.f, 0.f, 0.f, 0.f, 0.f};

    for (int ch = 0; ch < ND; ch += 256) {
        __syncthreads();
        {
            int j = ch + tid;
            float yj = yc[(b * ND + j) * NCH + c];
#pragma unroll
            for (int m = 0; m < NMIX; m++) {
                float4 p = g_pre[(bc * NMIX + m) * ND + j];
                sp[m][tid] = make_float4(p.x, p.y, p.z * yj, p.w * yj);
            }
        }
        __syncthreads();
#pragma unroll 4
        for (int k = 0; k < 32; k++) {
            int jj = slice * 32 + k;
#pragma unroll
            for (int m = 0; m < NMIX; m++) {
                float4 Pj = sp[m][jj];
                float t   = fmaf(Pi[m].x, Pj.x, Pi[m].y + Pj.y);
                float ccy = fmaf(Pi[m].w, Pj.w, Pi[m].z * Pj.z);
                f[m] = fmaf(exp2f(t), ccy, f[m]);
            }
        }
    }

#pragma unroll
    for (int m = 0; m < NMIX; m++) fpart[m][slice][il] = f[m];
    __syncthreads();

    if (slice == 0) {
        float yi = yc[(b * ND + i) * NCH + c];
        float ftot[NMIX];
#pragma unroll
        for (int m = 0; m < NMIX; m++) {
            float s = fpart[m][0][il];
#pragma unroll
            for (int s8 = 1; s8 < 8; s8++) s += fpart[m][s8][il];
            ftot[m] = fmaf(ZITTERf, yi, s);
        }
        float hk[NH];
#pragma unroll
        for (int k = 0; k < NH; k++) {
            float acc = b1[k];
#pragma unroll
            for (int m = 0; m < NMIX; m++) acc = fmaf(W1[k * 6 + m], ftot[m], acc);
            acc = fmaf(W1[k * 6 + 5], yi, acc);
            hk[k] = fmaxf(acc, 0.0f);
        }
#pragma unroll
        for (int k = 0; k < NH; k++) {
            float v = hk[k];
#pragma unroll
            for (int o = 16; o > 0; o >>= 1) v += __shfl_down_sync(0xffffffffu, v, o);
            if (il == 0) g_hpart[(bc * NFT + tile) * NH + k] = v;
        }
    }
}

// ---------------------------------------------------------------------------
// M: mean over nd, MLP tail, gumbel-softmax -> weights. Single small block.
// ---------------------------------------------------------------------------
__global__ void __launch_bounds__(256) k_mlp(const float* __restrict__ unif,
                                             const float* __restrict__ W2, const float* __restrict__ b2,
                                             const float* __restrict__ W3, const float* __restrict__ b3,
                                             const float* __restrict__ W4, const float* __restrict__ b4,
                                             const float* __restrict__ W5, const float* __restrict__ b5) {
    int tid = threadIdx.x;
    __shared__ float sHm[NB * NCH][NH];
    if (tid < NB * NCH * NH) {
        int bc = tid / NH, k = tid % NH;
        float s = 0.f;
#pragma unroll
        for (int t = 0; t < NFT; t++) s += g_hpart[(bc * NFT + t) * NH + k];
        sHm[bc][k] = s * (1.0f / ND);
    }
    __syncthreads();

    __shared__ float sLL[NB][NCH * NMIX];
    if (tid < NB) {
        int b = tid;
        float hm[NCH * NH];
#pragma unroll
        for (int c = 0; c < NCH; c++)
#pragma unroll
            for (int k = 0; k < NH; k++) hm[c * NH + k] = sHm[b * NCH + c][k];
        float h2[NH], h3[NH], h4[NH];
#pragma unroll
        for (int k = 0; k < NH; k++) {
            float a = b2[k];
            for (int j = 0; j < NCH * NH; j++) a = fmaf(W2[k * (NCH * NH) + j], hm[j], a);
            h2[k] = fmaxf(a, 0.f);
        }
#pragma unroll
        for (int k = 0; k < NH; k++) {
            float a = b3[k];
            for (int j = 0; j < NH; j++) a = fmaf(W3[k * NH + j], h2[j], a);
            h3[k] = fmaxf(a, 0.f);
        }
#pragma unroll
        for (int k = 0; k < NH; k++) {
            float a = b4[k];
            for (int j = 0; j < NH; j++) a = fmaf(W4[k * NH + j], h3[j], a);
            h4[k] = fmaxf(a, 0.f);
        }
#pragma unroll
        for (int o = 0; o < NCH * NMIX; o++) {
            float a = b5[o];
            for (int k = 0; k < NH; k++) a = fmaf(W5[o * NH + k], h4[k], a);
            sLL[b][o] = a;
        }
    }
    __syncthreads();

    if (tid < NB * NCH) {
        int b = tid / NCH, c = tid % NCH;
        float ws[NMIX] = {0.f, 0.f, 0.f, 0.f, 0.f};
        for (int s = 0; s < NS; s++) {
            float z[NMIX], mx = -1e30f;
#pragma unroll
            for (int m = 0; m < NMIX; m++) {
                float u = unif[((b * NS + s) * NCH + c) * NMIX + m];
                float g = -logf(-logf(u + 1e-20f));
                z[m] = (g + sLL[b][c * NMIX + m]) * 10.0f;
                mx = fmaxf(mx, z[m]);
            }
            float e[NMIX], sum = 0.f;
#pragma unroll
            for (int m = 0; m < NMIX; m++) { e[m] = expf(z[m] - mx); sum += e[m]; }
            float inv = 1.0f / sum;
#pragma unroll
            for (int m = 0; m < NMIX; m++) ws[m] = fmaf(e[m], inv, ws[m]);
        }
#pragma unroll
        for (int m = 0; m < NMIX; m++)
            g_wgt[tid * NMIX + m] = ws[m] * (1.0f / NS);
    }
}

// ---------------------------------------------------------------------------
// O: symmetric weighted reduction. 32x32 tiles, triangular pairs.
// 64 threads (8x8), 4x4 micro-tile per thread -> 8 LDS.128 per 16 evals
// (8 B/eval, half the L1 traffic of the 2x2 version which ncu showed
// L1-bound at 68.6%). Mixture weight folded into sJ. Mirror block via
// padded smem transpose.
// ---------------------------------------------------------------------------
__global__ void __launch_bounds__(64) k_out(const float* __restrict__ likerr,
                                            float* __restrict__ out) {
    int tid = threadIdx.x;
    int b   = blockIdx.y;
    int it  = c_pair_it[blockIdx.x];
    int jt  = c_pair_jt[blockIdx.x];

    __shared__ float4 sI[15 * 33];
    __shared__ float4 sJ[15 * 33];
    __shared__ float  sT[32 * 99];
    __shared__ float  sD[NCH];

    for (int idx = tid; idx < 15 * 32; idx += 64) {
        int p = idx >> 5, il = idx & 31;
        sI[p * 33 + il] = g_pre[(b * 15 + p) * ND + it * 32 + il];
        float4 pj = g_pre[(b * 15 + p) * ND + jt * 32 + il];
        float  w  = g_wgt[b * 15 + p];
        sJ[p * 33 + il] = make_float4(pj.x, pj.y, pj.z * w, pj.w * w);
    }
    if (tid < NCH) {
        float lk = fminf(fmaxf(likerr[tid], 0.1f), 1.0f);
        sD[tid] = ZITTERf + lk * lk;
    }
    __syncthreads();

    int tx = tid & 7, ty = tid >> 3;     // 8x8 threads
    float acc[NCH][16];
#pragma unroll
    for (int c = 0; c < NCH; c++)
#pragma unroll
        for (int k = 0; k < 16; k++) acc[c][k] = 0.f;

#pragma unroll
    for (int c = 0; c < NCH; c++) {
#pragma unroll
        for (int m = 0; m < NMIX; m++) {
            int p = c * NMIX + m;
            float4 Pi[4], Pj[4];
#pragma unroll
            for (int a = 0; a < 4; a++) {
                Pi[a] = sI[p * 33 + ty + 8 * a];
                Pj[a] = sJ[p * 33 + tx + 8 * a];
            }
#pragma unroll
            for (int a = 0; a < 4; a++)
#pragma unroll
                for (int d = 0; d < 4; d++) {
                    float t  = fmaf(Pi[a].x, Pj[d].x, Pi[a].y + Pj[d].y);
                    float cw = fmaf(Pi[a].w, Pj[d].w, Pi[a].z * Pj[d].z);
                    acc[c][a * 4 + d] = fmaf(exp2f(t), cw, acc[c][a * 4 + d]);
                }
        }
    }

    // direct block
#pragma unroll
    for (int a = 0; a < 4; a++) {
        int gi = it * 32 + ty + 8 * a;
#pragma unroll
        for (int d = 0; d < 4; d++) {
            int gj = jt * 32 + tx + 8 * d;
            int base = ((b * ND + gi) * ND + gj) * NCH;
            bool diag = (gi == gj);
#pragma unroll
            for (int c = 0; c < NCH; c++) {
                float v = acc[c][a * 4 + d];
                if (diag) v += sD[c];
                out[base + c] = v;
            }
        }
    }

    if (it != jt) {
#pragma unroll
        for (int a = 0; a < 4; a++)
#pragma unroll
            for (int d = 0; d < 4; d++)
#pragma unroll
                for (int c = 0; c < NCH; c++)
                    sT[(ty + 8 * a) * 99 + (tx + 8 * d) * 3 + c] = acc[c][a * 4 + d];
        __syncthreads();
#pragma unroll
        for (int a = 0; a < 4; a++) {
            int gi = jt * 32 + ty + 8 * a;
#pragma unroll
            for (int d = 0; d < 4; d++) {
                int gj = it * 32 + tx + 8 * d;
                int base = ((b * ND + gi) * ND + gj) * NCH;
#pragma unroll
                for (int c = 0; c < NCH; c++)
                    out[base + c] = sT[(tx + 8 * d) * 99 + (ty + 8 * a) * 3 + c];
            }
        }
    }
}

// ---------------------------------------------------------------------------
extern "C" void kernel_launch(void* const* d_in, const int* in_sizes, int n_in,
                              void* d_out, int out_size) {
    const float* xc      = (const float*)d_in[0];
    const float* yc      = (const float*)d_in[1];
    const float* mu      = (const float*)d_in[2];
    const float* inv_std = (const float*)d_in[3];
    const float* likerr  = (const float*)d_in[4];
    const float* unif    = (const float*)d_in[5];
    const float* W1 = (const float*)d_in[6],  *b1 = (const float*)d_in[7];
    const float* W2 = (const float*)d_in[8],  *b2 = (const float*)d_in[9];
    const float* W3 = (const float*)d_in[10], *b3 = (const float*)d_in[11];
    const float* W4 = (const float*)d_in[12], *b4 = (const float*)d_in[13];
    const float* W5 = (const float*)d_in[14], *b5 = (const float*)d_in[15];
    float* out = (float*)d_out;

    int npre = NB * NCH * NMIX * ND;
    k_pre<<<(npre + 255) / 256, 256>>>(xc, mu, inv_std);
    k_feat<<<dim3(NFT, NB * NCH), 256>>>(yc, W1, b1);
    k_mlp<<<1, 256>>>(unif, W2, b2, W3, b3, W4, b4, W5, b5);
    k_out<<<dim3(NPAIRS, NB), 64>>>(likerr, out);
}

// round 14
// speedup vs baseline: 1.3406x; 1.0910x over previous
#include <cuda_runtime.h>
#include <math.h>

#define NB   8
#define ND   768
#define NCH  3
#define NMIX 5
#define NS   10
#define NH   10

#define NT      24            // 32-wide tiles per ND
#define NPAIRS  300           // NT*(NT+1)/2 upper-triangular tile pairs

#define PI2f    6.283185307179586f
#define SQRT_L  1.2011224087864498f   // sqrt(log2(e))
#define ZITTERf 1e-4f

__device__ float4 g_pre[NB * NCH * NMIX * ND];        // {v, q, cos, sin} per (b,c,m,i)
__device__ float  g_feat[NB * NCH * ND * NMIX];       // feature[b,c,i,m] = sum_j K_m(i,j) y_j
__device__ float  g_hm[NB * NCH * NH];                // per-bc mean of relu(W1·tif)
__device__ float  g_wgt[NB * NCH * NMIX];             // gumbel-softmax mixture weights

// Triangular pair decode via constant LUT (branchless)
__constant__ unsigned char c_pair_it[NPAIRS] = {
    0,0,0,0,0,0,0,0,0,0,0,0,0,0,0,0,0,0,0,0,0,0,0,0,
    1,1,1,1,1,1,1,1,1,1,1,1,1,1,1,1,1,1,1,1,1,1,1,
    2,2,2,2,2,2,2,2,2,2,2,2,2,2,2,2,2,2,2,2,2,2,
    3,3,3,3,3,3,3,3,3,3,3,3,3,3,3,3,3,3,3,3,3,
    4,4,4,4,4,4,4,4,4,4,4,4,4,4,4,4,4,4,4,4,
    5,5,5,5,5,5,5,5,5,5,5,5,5,5,5,5,5,5,5,
    6,6,6,6,6,6,6,6,6,6,6,6,6,6,6,6,6,6,
    7,7,7,7,7,7,7,7,7,7,7,7,7,7,7,7,7,
    8,8,8,8,8,8,8,8,8,8,8,8,8,8,8,8,
    9,9,9,9,9,9,9,9,9,9,9,9,9,9,9,
    10,10,10,10,10,10,10,10,10,10,10,10,10,10,
    11,11,11,11,11,11,11,11,11,11,11,11,11,
    12,12,12,12,12,12,12,12,12,12,12,12,
    13,13,13,13,13,13,13,13,13,13,13,
    14,14,14,14,14,14,14,14,14,14,
    15,15,15,15,15,15,15,15,15,
    16,16,16,16,16,16,16,16,
    17,17,17,17,17,17,17,
    18,18,18,18,18,18,
    19,19,19,19,19,
    20,20,20,20,
    21,21,21,
    22,22,
    23
};
__constant__ unsigned char c_pair_jt[NPAIRS] = {
    0,1,2,3,4,5,6,7,8,9,10,11,12,13,14,15,16,17,18,19,20,21,22,23,
    1,2,3,4,5,6,7,8,9,10,11,12,13,14,15,16,17,18,19,20,21,22,23,
    2,3,4,5,6,7,8,9,10,11,12,13,14,15,16,17,18,19,20,21,22,23,
    3,4,5,6,7,8,9,10,11,12,13,14,15,16,17,18,19,20,21,22,23,
    4,5,6,7,8,9,10,11,12,13,14,15,16,17,18,19,20,21,22,23,
    5,6,7,8,9,10,11,12,13,14,15,16,17,18,19,20,21,22,23,
    6,7,8,9,10,11,12,13,14,15,16,17,18,19,20,21,22,23,
    7,8,9,10,11,12,13,14,15,16,17,18,19,20,21,22,23,
    8,9,10,11,12,13,14,15,16,17,18,19,20,21,22,23,
    9,10,11,12,13,14,15,16,17,18,19,20,21,22,23,
    10,11,12,13,14,15,16,17,18,19,20,21,22,23,
    11,12,13,14,15,16,17,18,19,20,21,22,23,
    12,13,14,15,16,17,18,19,20,21,22,23,
    13,14,15,16,17,18,19,20,21,22,23,
    14,15,16,17,18,19,20,21,22,23,
    15,16,17,18,19,20,21,22,23,
    16,17,18,19,20,21,22,23,
    17,18,19,20,21,22,23,
    18,19,20,21,22,23,
    19,20,21,22,23,
    20,21,22,23,
    21,22,23,
    22,23,
    23
};

// ---------------------------------------------------------------------------
// P: per-point precompute.
// ---------------------------------------------------------------------------
__global__ void k_pre(const float* __restrict__ xc,
                      const float* __restrict__ mu,
                      const float* __restrict__ inv_std) {
    int idx = blockIdx.x * blockDim.x + threadIdx.x;
    if (idx >= NB * NCH * NMIX * ND) return;
    int i = idx % ND;
    int m = (idx / ND) % NMIX;
    int c = (idx / (ND * NMIX)) % NCH;
    int b = idx / (ND * NMIX * NCH);
    float x = xc[(b * ND + i) * NCH + c];
    float a = PI2f * inv_std[m];
    float v = a * x * SQRT_L;
    float q = -0.5f * v * v;
    float s, co;
    sincosf(PI2f * mu[m] * x, &s, &co);
    g_pre[idx] = make_float4(v, q, co, s);
}

// ---------------------------------------------------------------------------
// FA: feature matvec, one m per block-z. grid (24 i-tiles, 24 bc, 5 m),
// 256 threads = 8 warps x 32 lanes. Each warp owns 4 i's; lanes parallel
// over j (24 j's per lane). One LDS.128 per (j) serves 4 evals -> 4 B/eval
// (k_feat was LDS-bound at 16 B/eval). Warp-shfl reduce (deterministic).
// ---------------------------------------------------------------------------
__global__ void __launch_bounds__(256) k_featA(const float* __restrict__ yc) {
    int tile = blockIdx.x;
    int bc   = blockIdx.y;
    int m    = blockIdx.z;
    int tid  = threadIdx.x;
    int w    = tid >> 5, lane = tid & 31;
    int b = bc / NCH, c = bc % NCH;
    int i0 = tile * 32 + w * 4;

    __shared__ float4 sp[256];   // {v, q, c*y, s*y} for current j-chunk

    float4 Pi[4];
#pragma unroll
    for (int ii = 0; ii < 4; ii++)
        Pi[ii] = g_pre[(bc * NMIX + m) * ND + i0 + ii];

    float f[4] = {0.f, 0.f, 0.f, 0.f};

    for (int ch = 0; ch < ND; ch += 256) {
        __syncthreads();
        {
            int j = ch + tid;
            float yj = yc[(b * ND + j) * NCH + c];
            float4 p = g_pre[(bc * NMIX + m) * ND + j];
            sp[tid] = make_float4(p.x, p.y, p.z * yj, p.w * yj);
        }
        __syncthreads();
#pragma unroll
        for (int k = 0; k < 8; k++) {
            float4 Pj = sp[lane + 32 * k];
#pragma unroll
            for (int ii = 0; ii < 4; ii++) {
                float t   = fmaf(Pi[ii].x, Pj.x, Pi[ii].y + Pj.y);
                float ccy = fmaf(Pi[ii].w, Pj.w, Pi[ii].z * Pj.z);
                f[ii] = fmaf(exp2f(t), ccy, f[ii]);
            }
        }
    }

#pragma unroll
    for (int o = 16; o > 0; o >>= 1)
#pragma unroll
        for (int ii = 0; ii < 4; ii++)
            f[ii] += __shfl_down_sync(0xffffffffu, f[ii], o);

    if (lane == 0) {
#pragma unroll
        for (int ii = 0; ii < 4; ii++)
            g_feat[(bc * ND + i0 + ii) * NMIX + m] = f[ii];
    }
}

// ---------------------------------------------------------------------------
// FB: per-(b,i,c): ftot = feat + zitter*y; hk = relu(W1·[ftot,y]+b1);
// deterministic block mean over the 768 i's of each bc. grid (24 bc), 256 thr.
// ---------------------------------------------------------------------------
__global__ void __launch_bounds__(256) k_featB(const float* __restrict__ yc,
                                               const float* __restrict__ W1,
                                               const float* __restrict__ b1) {
    int bc  = blockIdx.x;
    int tid = threadIdx.x;
    int b = bc / NCH, c = bc % NCH;

    float hs[NH];
#pragma unroll
    for (int k = 0; k < NH; k++) hs[k] = 0.f;

    for (int i = tid; i < ND; i += 256) {
        float yi = yc[(b * ND + i) * NCH + c];
        float ft[NMIX];
#pragma unroll
        for (int m = 0; m < NMIX; m++)
            ft[m] = fmaf(ZITTERf, yi, g_feat[(bc * ND + i) * NMIX + m]);
#pragma unroll
        for (int k = 0; k < NH; k++) {
            float a = b1[k];
#pragma unroll
            for (int m = 0; m < NMIX; m++) a = fmaf(W1[k * 6 + m], ft[m], a);
            a = fmaf(W1[k * 6 + 5], yi, a);
            hs[k] += fmaxf(a, 0.f);
        }
    }

    __shared__ float red[8][NH];
    int lane = tid & 31, w = tid >> 5;
#pragma unroll
    for (int k = 0; k < NH; k++) {
        float v = hs[k];
#pragma unroll
        for (int o = 16; o > 0; o >>= 1) v += __shfl_down_sync(0xffffffffu, v, o);
        if (lane == 0) red[w][k] = v;
    }
    __syncthreads();
    if (tid < NH) {
        float s = 0.f;
#pragma unroll
        for (int ww = 0; ww < 8; ww++) s += red[ww][tid];
        g_hm[bc * NH + tid] = s * (1.0f / ND);
    }
}

// ---------------------------------------------------------------------------
// M: MLP tail + gumbel-softmax -> weights. Single small block.
// ---------------------------------------------------------------------------
__global__ void __launch_bounds__(256) k_mlp(const float* __restrict__ unif,
                                             const float* __restrict__ W2, const float* __restrict__ b2,
                                             const float* __restrict__ W3, const float* __restrict__ b3,
                                             const float* __restrict__ W4, const float* __restrict__ b4,
                                             const float* __restrict__ W5, const float* __restrict__ b5) {
    int tid = threadIdx.x;
    __shared__ float sLL[NB][NCH * NMIX];
    if (tid < NB) {
        int b = tid;
        float hm[NCH * NH];
#pragma unroll
        for (int c = 0; c < NCH; c++)
#pragma unroll
            for (int k = 0; k < NH; k++) hm[c * NH + k] = g_hm[(b * NCH + c) * NH + k];
        float h2[NH], h3[NH], h4[NH];
#pragma unroll
        for (int k = 0; k < NH; k++) {
            float a = b2[k];
            for (int j = 0; j < NCH * NH; j++) a = fmaf(W2[k * (NCH * NH) + j], hm[j], a);
            h2[k] = fmaxf(a, 0.f);
        }
#pragma unroll
        for (int k = 0; k < NH; k++) {
            float a = b3[k];
            for (int j = 0; j < NH; j++) a = fmaf(W3[k * NH + j], h2[j], a);
            h3[k] = fmaxf(a, 0.f);
        }
#pragma unroll
        for (int k = 0; k < NH; k++) {
            float a = b4[k];
            for (int j = 0; j < NH; j++) a = fmaf(W4[k * NH + j], h3[j], a);
            h4[k] = fmaxf(a, 0.f);
        }
#pragma unroll
        for (int o = 0; o < NCH * NMIX; o++) {
            float a = b5[o];
            for (int k = 0; k < NH; k++) a = fmaf(W5[o * NH + k], h4[k], a);
            sLL[b][o] = a;
        }
    }
    __syncthreads();

    if (tid < NB * NCH) {
        int b = tid / NCH, c = tid % NCH;
        float ws[NMIX] = {0.f, 0.f, 0.f, 0.f, 0.f};
        for (int s = 0; s < NS; s++) {
            float z[NMIX], mx = -1e30f;
#pragma unroll
            for (int m = 0; m < NMIX; m++) {
                float u = unif[((b * NS + s) * NCH + c) * NMIX + m];
                float g = -logf(-logf(u + 1e-20f));
                z[m] = (g + sLL[b][c * NMIX + m]) * 10.0f;
                mx = fmaxf(mx, z[m]);
            }
            float e[NMIX], sum = 0.f;
#pragma unroll
            for (int m = 0; m < NMIX; m++) { e[m] = expf(z[m] - mx); sum += e[m]; }
            float inv = 1.0f / sum;
#pragma unroll
            for (int m = 0; m < NMIX; m++) ws[m] = fmaf(e[m], inv, ws[m]);
        }
#pragma unroll
        for (int m = 0; m < NMIX; m++)
            g_wgt[tid * NMIX + m] = ws[m] * (1.0f / NS);
    }
}

// ---------------------------------------------------------------------------
// O: symmetric weighted reduction. 32x32 tiles, triangular pairs,
// 128 threads (16x8), 4i x 2j micro-tile -> 6 LDS.128 per 8 evals (12 B/eval).
// smem UNION: transpose staging reuses the tile buffer after compute
// (15.9 KB total vs 29 KB -> ~6 blocks/SM vs the occ=19% that sank R9's
// 64-thread version). Mirror block via padded transpose, coalesced stores.
// ---------------------------------------------------------------------------
__global__ void __launch_bounds__(128) k_out(const float* __restrict__ likerr,
                                             float* __restrict__ out) {
    int tid = threadIdx.x;
    int b   = blockIdx.y;
    int it  = c_pair_it[blockIdx.x];
    int jt  = c_pair_jt[blockIdx.x];

    __shared__ char smem_buf[2 * 15 * 33 * 16];   // 15840 B; sT (12672 B) aliases
    float4* sI = (float4*)smem_buf;
    float4* sJ = sI + 15 * 33;
    float*  sT = (float*)smem_buf;                // valid only after compute
    __shared__ float sD[NCH];

    for (int idx = tid; idx < 15 * 32; idx += 128) {
        int p = idx >> 5, il = idx & 31;
        sI[p * 33 + il] = g_pre[(b * 15 + p) * ND + it * 32 + il];
        float4 pj = g_pre[(b * 15 + p) * ND + jt * 32 + il];
        float  w  = g_wgt[b * 15 + p];
        sJ[p * 33 + il] = make_float4(pj.x, pj.y, pj.z * w, pj.w * w);
    }
    if (tid < NCH) {
        float lk = fminf(fmaxf(likerr[tid], 0.1f), 1.0f);
        sD[tid] = ZITTERf + lk * lk;
    }
    __syncthreads();

    int tx = tid & 15, ty = tid >> 4;   // 16 (j) x 8 (i)
    float acc[NCH][8];                  // [c][a*2+d], a=0..3 (i), d=0..1 (j)
#pragma unroll
    for (int c = 0; c < NCH; c++)
#pragma unroll
        for (int k = 0; k < 8; k++) acc[c][k] = 0.f;

#pragma unroll
    for (int c = 0; c < NCH; c++) {
#pragma unroll
        for (int m = 0; m < NMIX; m++) {
            int p = c * NMIX + m;
            float4 Pi[4], Pj[2];
#pragma unroll
            for (int a = 0; a < 4; a++) Pi[a] = sI[p * 33 + ty + 8 * a];
#pragma unroll
            for (int d = 0; d < 2; d++) Pj[d] = sJ[p * 33 + tx + 16 * d];
#pragma unroll
            for (int a = 0; a < 4; a++)
#pragma unroll
                for (int d = 0; d < 2; d++) {
                    float t  = fmaf(Pi[a].x, Pj[d].x, Pi[a].y + Pj[d].y);
                    float cw = fmaf(Pi[a].w, Pj[d].w, Pi[a].z * Pj[d].z);
                    acc[c][a * 2 + d] = fmaf(exp2f(t), cw, acc[c][a * 2 + d]);
                }
        }
    }

    // direct block (rows it-tile, cols jt-tile), coalesced in tx
#pragma unroll
    for (int a = 0; a < 4; a++) {
        int gi = it * 32 + ty + 8 * a;
#pragma unroll
        for (int d = 0; d < 2; d++) {
            int gj = jt * 32 + tx + 16 * d;
            int base = ((b * ND + gi) * ND + gj) * NCH;
            bool diag = (gi == gj);
#pragma unroll
            for (int c = 0; c < NCH; c++) {
                float v = acc[c][a * 2 + d];
                if (diag) v += sD[c];
                out[base + c] = v;
            }
        }
    }

    if (it != jt) {
        __syncthreads();   // everyone done reading sI/sJ before aliasing as sT
#pragma unroll
        for (int a = 0; a < 4; a++)
#pragma unroll
            for (int d = 0; d < 2; d++)
#pragma unroll
                for (int c = 0; c < NCH; c++)
                    sT[(ty + 8 * a) * 99 + (tx + 16 * d) * 3 + c] = acc[c][a * 2 + d];
        __syncthreads();
        // mirror block (rows jt-tile, cols it-tile): M[r][s] = block[s][r]
#pragma unroll
        for (int a = 0; a < 4; a++) {
            int r = ty + 8 * a;
            int gi = jt * 32 + r;
#pragma unroll
            for (int d = 0; d < 2; d++) {
                int s = tx + 16 * d;
                int gj = it * 32 + s;
                int base = ((b * ND + gi) * ND + gj) * NCH;
#pragma unroll
                for (int c = 0; c < NCH; c++)
                    out[base + c] = sT[s * 99 + r * 3 + c];
            }
        }
    }
}

// ---------------------------------------------------------------------------
extern "C" void kernel_launch(void* const* d_in, const int* in_sizes, int n_in,
                              void* d_out, int out_size) {
    const float* xc      = (const float*)d_in[0];
    const float* yc      = (const float*)d_in[1];
    const float* mu      = (const float*)d_in[2];
    const float* inv_std = (const float*)d_in[3];
    const float* likerr  = (const float*)d_in[4];
    const float* unif    = (const float*)d_in[5];
    const float* W1 = (const float*)d_in[6],  *b1 = (const float*)d_in[7];
    const float* W2 = (const float*)d_in[8],  *b2 = (const float*)d_in[9];
    const float* W3 = (const float*)d_in[10], *b3 = (const float*)d_in[11];
    const float* W4 = (const float*)d_in[12], *b4 = (const float*)d_in[13];
    const float* W5 = (const float*)d_in[14], *b5 = (const float*)d_in[15];
    float* out = (float*)d_out;

    int npre = NB * NCH * NMIX * ND;
    k_pre<<<(npre + 255) / 256, 256>>>(xc, mu, inv_std);
    k_featA<<<dim3(NT, NB * NCH, NMIX), 256>>>(yc);
    k_featB<<<NB * NCH, 256>>>(yc, W1, b1);
    k_mlp<<<1, 256>>>(unif, W2, b2, W3, b3, W4, b4, W5, b5);
    k_out<<<dim3(NPAIRS, NB), 128>>>(likerr, out);
}